// round 4
// baseline (speedup 1.0000x reference)
#include <cuda_runtime.h>

// Scratch (no device allocation allowed).
// Transposed layout: g_part[entry][block]; blocks 4b..4b+3 belong to batch b,
// so each batch's 4 partials of one entry form a single aligned float4.
__device__ __align__(16) float g_part[36][16];
__device__ unsigned int g_count = 0;

// Weight of each packed upper-triangular entry e=(i,j), i<=j, of the 8x8
// second-moment matrix M in loss_b = sum_e w_e * M_b[e]^2:
//   both in P-block (0..3): diag 1, off-diag 2   (||PP^T||_F^2)
//   i in P, j in S (4..7):  -2                   (-2||PS^T||_F^2)
//   both in S-block:        diag 1, off-diag 2   (||SS^T||_F^2)
__constant__ float c_w[36] = {
    1.f, 2.f, 2.f, 2.f, -2.f, -2.f, -2.f, -2.f,   // i=0
    1.f, 2.f, 2.f, -2.f, -2.f, -2.f, -2.f,        // i=1
    1.f, 2.f, -2.f, -2.f, -2.f, -2.f,             // i=2
    1.f, -2.f, -2.f, -2.f, -2.f,                  // i=3
    1.f, 2.f, 2.f, 2.f,                           // i=4
    1.f, 2.f, 2.f,                                // i=5
    1.f, 2.f,                                     // i=6
    1.f                                           // i=7
};

// grid = 16 blocks (4 slices per batch), 256 threads; each thread owns one
// float4 group (4 spatial positions). v_n = [p_n/||p_n||, s_n/||s_n||] in R^8;
// block accumulates 36 unique entries of sum_n v_n v_n^T for its slice.
// Last arriving block's warp 0 reduces per-BATCH and evaluates
//   loss = sum_b (||PP^T||^2 - 2||PS^T||^2 + ||SS^T||^2) / (B*N*N)
// via the exact identity sum_nm (a_n.a_m)(b_n.b_m) = ||A B^T||_F^2.
__global__ void __launch_bounds__(256, 1)
cosine_ssm_fused_kernel(const float* __restrict__ xp,
                        const float* __restrict__ xs,
                        float* __restrict__ out)
{
    constexpr int N = 4096;
    const int blk   = blockIdx.x;
    const int b     = blk >> 2;       // batch
    const int slice = blk & 3;        // quarter of the spatial dim
    const int t     = threadIdx.x;

    const float* pb = xp + b * 4 * N;
    const float* sb = xs + b * 4 * N;
    const int g = (slice * 1024) + t * 4;   // starting spatial index

    float pv[4][4], sv[4][4];
#pragma unroll
    for (int c = 0; c < 4; ++c) {
        float4 a = *reinterpret_cast<const float4*>(pb + c * N + g);
        pv[c][0] = a.x; pv[c][1] = a.y; pv[c][2] = a.z; pv[c][3] = a.w;
        float4 q = *reinterpret_cast<const float4*>(sb + c * N + g);
        sv[c][0] = q.x; sv[c][1] = q.y; sv[c][2] = q.z; sv[c][3] = q.w;
    }

    float acc[36];
#pragma unroll
    for (int i = 0; i < 36; ++i) acc[i] = 0.0f;

#pragma unroll
    for (int k = 0; k < 4; ++k) {
        float sumsq_p = pv[0][k] * pv[0][k] + pv[1][k] * pv[1][k]
                      + pv[2][k] * pv[2][k] + pv[3][k] * pv[3][k];
        float sumsq_s = sv[0][k] * sv[0][k] + sv[1][k] * sv[1][k]
                      + sv[2][k] * sv[2][k] + sv[3][k] * sv[3][k];
        // x / max(||x||, 1e-12)  ==  x * rsqrt(max(||x||^2, 1e-24))
        float ip = rsqrtf(fmaxf(sumsq_p, 1e-24f));
        float is = rsqrtf(fmaxf(sumsq_s, 1e-24f));
        float v[8];
#pragma unroll
        for (int c = 0; c < 4; ++c) {
            v[c]     = pv[c][k] * ip;
            v[4 + c] = sv[c][k] * is;
        }
        int idx = 0;
#pragma unroll
        for (int i = 0; i < 8; ++i)
#pragma unroll
            for (int jj = i; jj < 8; ++jj)
                acc[idx++] += v[i] * v[jj];
    }

    // Intra-warp tree reduction of the 36 accumulators.
#pragma unroll
    for (int off = 16; off > 0; off >>= 1)
#pragma unroll
        for (int i = 0; i < 36; ++i)
            acc[i] += __shfl_down_sync(0xffffffffu, acc[i], off);

    __shared__ float red[8][36];
    const int warp = t >> 5;
    const int lane = t & 31;
    if (lane == 0) {
#pragma unroll
        for (int i = 0; i < 36; ++i) red[warp][i] = acc[i];
    }
    __syncthreads();

    // Cross-warp reduce: 36 threads, one entry each -> per-block partial.
    if (t < 36) {
        float s = red[0][t];
#pragma unroll
        for (int w = 1; w < 8; ++w) s += red[w][t];
        g_part[t][blk] = s;
    }
    __syncthreads();          // all block writes happen-before the fence below

    // ---- cross-block handoff, warp 0 only ----
    if (warp != 0) return;

    unsigned int old = 0;
    if (lane == 0) {
        __threadfence();      // publish this block's g_part column (cumulative)
        old = atomicAdd(&g_count, 1u);
    }
    old = __shfl_sync(0xffffffffu, old, 0);
    if (old != 15u) return;

    // ---- last block, warp 0: per-BATCH reduce + weighted square ----
    __threadfence();          // acquire: make all blocks' g_part visible

    // lane l handles entry l; lanes 0..3 also handle entries 32..35.
    // Each float4 = one batch's 4 block-partials of this entry.
    float val = 0.0f;
    {
        const float4* r = reinterpret_cast<const float4*>(g_part[lane]);
        float ssum = 0.0f;
#pragma unroll
        for (int bb = 0; bb < 4; ++bb) {
            float4 q = __ldcg(r + bb);               // L2-scoped (skip L1)
            float m = (q.x + q.y) + (q.z + q.w);     // batch bb moment entry
            ssum += m * m;
        }
        val = c_w[lane] * ssum;
    }
    if (lane < 4) {
        const float4* r = reinterpret_cast<const float4*>(g_part[32 + lane]);
        float ssum = 0.0f;
#pragma unroll
        for (int bb = 0; bb < 4; ++bb) {
            float4 q = __ldcg(r + bb);
            float m = (q.x + q.y) + (q.z + q.w);
            ssum += m * m;
        }
        val += c_w[32 + lane] * ssum;
    }

#pragma unroll
    for (int off = 16; off > 0; off >>= 1)
        val += __shfl_down_sync(0xffffffffu, val, off);

    if (lane == 0) {
        out[0] = val * (1.0f / (4.0f * 4096.0f * 4096.0f));
        g_count = 0;   // reset for the next graph replay
    }
}

extern "C" void kernel_launch(void* const* d_in, const int* in_sizes, int n_in,
                              void* d_out, int out_size)
{
    const float* xp = (const float*)d_in[0];  // x_pred [4,4,64,64] fp32
    const float* xs = (const float*)d_in[1];  // x_src  [4,4,64,64] fp32
    cosine_ssm_fused_kernel<<<16, 256>>>(xp, xs, (float*)d_out);
}

// round 5
// speedup vs baseline: 1.0590x; 1.0590x over previous
#include <cuda_runtime.h>

// Scratch (no device allocation allowed).
// Transposed layout: g_part[entry][block]; blocks 8b..8b+7 belong to batch b,
// so each batch's 8 partials of one entry are two aligned float4s.
__device__ __align__(16) float g_part[36][32];
__device__ unsigned int g_count = 0;

// Weight of each packed upper-triangular entry e=(i,j), i<=j, of the 8x8
// second-moment matrix M in loss_b = sum_e w_e * M_b[e]^2:
//   both in P-block (0..3): diag 1, off-diag 2   (||PP^T||_F^2)
//   i in P, j in S (4..7):  -2                   (-2||PS^T||_F^2)
//   both in S-block:        diag 1, off-diag 2   (||SS^T||_F^2)
__constant__ float c_w[36] = {
    1.f, 2.f, 2.f, 2.f, -2.f, -2.f, -2.f, -2.f,   // i=0
    1.f, 2.f, 2.f, -2.f, -2.f, -2.f, -2.f,        // i=1
    1.f, 2.f, -2.f, -2.f, -2.f, -2.f,             // i=2
    1.f, -2.f, -2.f, -2.f, -2.f,                  // i=3
    1.f, 2.f, 2.f, 2.f,                           // i=4
    1.f, 2.f, 2.f,                                // i=5
    1.f, 2.f,                                     // i=6
    1.f                                           // i=7
};

// grid = 32 blocks (8 slices per batch), 128 threads (1 warp per SMSP).
// Each thread owns one float4 group (4 spatial positions).
// v_n = [p_n/||p_n||, s_n/||s_n||] in R^8; block accumulates the 36 unique
// entries of sum_n v_n v_n^T for its slice. Last arriving block's warp 0
// reduces per-BATCH and evaluates
//   loss = sum_b (||PP^T||^2 - 2||PS^T||^2 + ||SS^T||^2) / (B*N*N)
// via the exact identity sum_nm (a_n.a_m)(b_n.b_m) = ||A B^T||_F^2.
__global__ void __launch_bounds__(128, 1)
cosine_ssm_fused_kernel(const float* __restrict__ xp,
                        const float* __restrict__ xs,
                        float* __restrict__ out)
{
    constexpr int N = 4096;
    const int blk   = blockIdx.x;
    const int b     = blk >> 3;       // batch (8 blocks per batch)
    const int slice = blk & 7;        // eighth of the spatial dim
    const int t     = threadIdx.x;

    const float* pb = xp + b * 4 * N;
    const float* sb = xs + b * 4 * N;
    const int g = (slice * 512) + t * 4;   // starting spatial index

    float pv[4][4], sv[4][4];
#pragma unroll
    for (int c = 0; c < 4; ++c) {
        float4 a = *reinterpret_cast<const float4*>(pb + c * N + g);
        pv[c][0] = a.x; pv[c][1] = a.y; pv[c][2] = a.z; pv[c][3] = a.w;
        float4 q = *reinterpret_cast<const float4*>(sb + c * N + g);
        sv[c][0] = q.x; sv[c][1] = q.y; sv[c][2] = q.z; sv[c][3] = q.w;
    }

    float acc[36];
#pragma unroll
    for (int i = 0; i < 36; ++i) acc[i] = 0.0f;

#pragma unroll
    for (int k = 0; k < 4; ++k) {
        float sumsq_p = pv[0][k] * pv[0][k] + pv[1][k] * pv[1][k]
                      + pv[2][k] * pv[2][k] + pv[3][k] * pv[3][k];
        float sumsq_s = sv[0][k] * sv[0][k] + sv[1][k] * sv[1][k]
                      + sv[2][k] * sv[2][k] + sv[3][k] * sv[3][k];
        // x / max(||x||, 1e-12)  ==  x * rsqrt(max(||x||^2, 1e-24))
        float ip = rsqrtf(fmaxf(sumsq_p, 1e-24f));
        float is = rsqrtf(fmaxf(sumsq_s, 1e-24f));
        float v[8];
#pragma unroll
        for (int c = 0; c < 4; ++c) {
            v[c]     = pv[c][k] * ip;
            v[4 + c] = sv[c][k] * is;
        }
        int idx = 0;
#pragma unroll
        for (int i = 0; i < 8; ++i)
#pragma unroll
            for (int jj = i; jj < 8; ++jj)
                acc[idx++] += v[i] * v[jj];
    }

    // Partial warp reduce: 2 butterfly rounds only (72 SHFL instead of 180).
    // After offsets 16 and 8, lanes 0..7 hold sums over lanes {l, l+8, l+16, l+24}.
#pragma unroll
    for (int off = 16; off >= 8; off >>= 1)
#pragma unroll
        for (int i = 0; i < 36; ++i)
            acc[i] += __shfl_down_sync(0xffffffffu, acc[i], off);

    // Padded smem: stride 37 (== 5 mod 32) -> conflict-free column access.
    __shared__ float red[32][37];
    const int warp = t >> 5;
    const int lane = t & 31;
    if (lane < 8) {
        float* row = red[warp * 8 + lane];
#pragma unroll
        for (int i = 0; i < 36; ++i) row[i] = acc[i];
    }
    __syncthreads();

    // Block reduce: 36 threads, one entry each, sum the 32 rows (pipelined LDS).
    if (t < 36) {
        float s = 0.0f;
#pragma unroll
        for (int r = 0; r < 32; ++r) s += red[r][t];
        g_part[t][blk] = s;
    }
    __syncthreads();          // all block writes happen-before the fence below

    // ---- cross-block handoff, warp 0 only ----
    if (warp != 0) return;

    unsigned int old = 0;
    if (lane == 0) {
        __threadfence();      // publish this block's g_part column
        old = atomicAdd(&g_count, 1u);
    }
    old = __shfl_sync(0xffffffffu, old, 0);
    if (old != 31u) return;

    // ---- last block, warp 0: per-BATCH reduce + weighted square ----
    __threadfence();          // acquire: make all blocks' g_part visible

    // lane l handles entry l; lanes 0..3 also handle entries 32..35.
    // Each batch's 8 block-partials of one entry = two float4s.
    float val = 0.0f;
    {
        const float4* r = reinterpret_cast<const float4*>(g_part[lane]);
        float ssum = 0.0f;
#pragma unroll
        for (int bb = 0; bb < 4; ++bb) {
            float4 q0 = __ldcg(r + bb * 2);
            float4 q1 = __ldcg(r + bb * 2 + 1);
            float m = ((q0.x + q0.y) + (q0.z + q0.w))
                    + ((q1.x + q1.y) + (q1.z + q1.w));
            ssum += m * m;
        }
        val = c_w[lane] * ssum;
    }
    if (lane < 4) {
        const float4* r = reinterpret_cast<const float4*>(g_part[32 + lane]);
        float ssum = 0.0f;
#pragma unroll
        for (int bb = 0; bb < 4; ++bb) {
            float4 q0 = __ldcg(r + bb * 2);
            float4 q1 = __ldcg(r + bb * 2 + 1);
            float m = ((q0.x + q0.y) + (q0.z + q0.w))
                    + ((q1.x + q1.y) + (q1.z + q1.w));
            ssum += m * m;
        }
        val += c_w[32 + lane] * ssum;
    }

#pragma unroll
    for (int off = 16; off > 0; off >>= 1)
        val += __shfl_down_sync(0xffffffffu, val, off);

    if (lane == 0) {
        out[0] = val * (1.0f / (4.0f * 4096.0f * 4096.0f));
        g_count = 0;   // reset for the next graph replay
    }
}

extern "C" void kernel_launch(void* const* d_in, const int* in_sizes, int n_in,
                              void* d_out, int out_size)
{
    const float* xp = (const float*)d_in[0];  // x_pred [4,4,64,64] fp32
    const float* xs = (const float*)d_in[1];  // x_src  [4,4,64,64] fp32
    cosine_ssm_fused_kernel<<<32, 128>>>(xp, xs, (float*)d_out);
}